// round 3
// baseline (speedup 1.0000x reference)
#include <cuda_runtime.h>
#include <cuda_bf16.h>

// ---------------------------------------------------------------------------
// OrdinalPeakedCELoss: B=4M rows, K=9.  Single fused streaming reduction.
//   loss_row = nll*INV_LOGK + ALPHA*(W_FAR*farm + W_TAIL*tail
//                                    + W_LPEAK*lpeak + W_EMD*emd2)
//   out = mean over rows.
// Pass 1: grid-stride rows -> per-block float partial sums (fixed 4096 blocks)
// Pass 2: one block sums partials in double, writes out[0] = total / B.
// Deterministic (fixed grid, fixed reduction tree, no atomics).
// ---------------------------------------------------------------------------

#define KCLS 9

static __constant__ float c_cw[KCLS] = {
    3.0f/95.0f, 7.0f/95.0f, 10.0f/95.0f, 10.0f/95.0f, 10.0f/95.0f,
    10.0f/95.0f, 10.0f/95.0f, 10.0f/95.0f, 25.0f/95.0f
};

#define ALPHA_C      0.4f
#define W_FAR_C      7.0f
#define DELTA_FAR_C  0.15f
#define W_TAIL_C     9.0f
#define W_LPEAK_C    12.0f
#define PROB_MARGIN_C 0.35f
#define W_EMD_C      1.2f
#define EPS_C        1e-8f
#define INV_LOGK_C   0.45511961331341866f   /* 1/ln(9) */

#define NBLOCKS 4096
#define NTHREADS 256

__device__ float g_partials[NBLOCKS];

__device__ __forceinline__ float row_loss(const float* __restrict__ lp, int y) {
    float l[KCLS];
#pragma unroll
    for (int k = 0; k < KCLS; ++k) l[k] = lp[k];

    // max
    float m = l[0];
#pragma unroll
    for (int k = 1; k < KCLS; ++k) m = fmaxf(m, l[k]);

    // exp, sum, select l[y] without dynamic indexing
    float e[KCLS];
    float S = 0.0f, ly = 0.0f;
#pragma unroll
    for (int k = 0; k < KCLS; ++k) {
        float ek = __expf(l[k] - m);
        e[k] = ek;
        S += ek;
        if (k == y) ly = l[k];
    }
    float nll = __logf(S) - (ly - m);

    float invS = __frcp_rn(S);

    // clamp_min(eps) + renormalize
    float S2 = 0.0f;
#pragma unroll
    for (int k = 0; k < KCLS; ++k) {
        float p = fmaxf(e[k] * invS, EPS_C);
        e[k] = p;
        S2 += p;
    }
    float inv2 = __frcp_rn(S2);

    float py = 0.0f, pl = 0.0f, pr = 0.0f;
    float farmax = 0.0f, tail = 0.0f, emd = 0.0f, csum = 0.0f;
#pragma unroll
    for (int k = 0; k < KCLS; ++k) {
        float p = e[k] * inv2;
        int d = k - y;
        int ad = (d < 0) ? -d : d;
        if (ad == 0)      py = p;
        else if (d == -1) pl = p;
        else if (d == 1)  pr = p;
        else {
            farmax = fmaxf(farmax, p);
            float w = (float)(ad - 1);
            tail += p * (w * w * w);
        }
        csum += p;
        float t = (k <= y) ? 1.0f : 0.0f;
        float diff = csum - t;
        emd += diff * diff * c_cw[k];
    }

    float farm  = fmaxf(farmax - py + DELTA_FAR_C, 0.0f);
    float nmax  = fmaxf(pl, pr);
    float lpeak = fmaxf(nmax - py + PROB_MARGIN_C, 0.0f);

    return nll * INV_LOGK_C
         + ALPHA_C * (W_FAR_C * farm + W_TAIL_C * tail
                      + W_LPEAK_C * lpeak + W_EMD_C * emd);
}

__global__ __launch_bounds__(NTHREADS, 8)
void opcel_pass1(const float* __restrict__ logits,
                 const int*   __restrict__ y,
                 int B) {
    float acc = 0.0f;
    int stride = gridDim.x * blockDim.x;
    for (int r = blockIdx.x * blockDim.x + threadIdx.x; r < B; r += stride) {
        acc += row_loss(logits + (long long)r * KCLS, y[r]);
    }

    // warp reduce
#pragma unroll
    for (int off = 16; off > 0; off >>= 1)
        acc += __shfl_down_sync(0xFFFFFFFFu, acc, off);

    __shared__ float s[NTHREADS / 32];
    int lane = threadIdx.x & 31;
    int wid  = threadIdx.x >> 5;
    if (lane == 0) s[wid] = acc;
    __syncthreads();

    if (wid == 0) {
        float v = (lane < NTHREADS / 32) ? s[lane] : 0.0f;
#pragma unroll
        for (int off = 4; off > 0; off >>= 1)
            v += __shfl_down_sync(0xFFFFFFFFu, v, off);
        if (lane == 0) g_partials[blockIdx.x] = v;
    }
}

__global__ __launch_bounds__(NTHREADS, 1)
void opcel_pass2(float* __restrict__ out, int B) {
    double acc = 0.0;
    for (int i = threadIdx.x; i < NBLOCKS; i += NTHREADS)
        acc += (double)g_partials[i];

#pragma unroll
    for (int off = 16; off > 0; off >>= 1)
        acc += __shfl_down_sync(0xFFFFFFFFu, acc, off);

    __shared__ double s[NTHREADS / 32];
    int lane = threadIdx.x & 31;
    int wid  = threadIdx.x >> 5;
    if (lane == 0) s[wid] = acc;
    __syncthreads();

    if (wid == 0) {
        double v = (lane < NTHREADS / 32) ? s[lane] : 0.0;
#pragma unroll
        for (int off = 4; off > 0; off >>= 1)
            v += __shfl_down_sync(0xFFFFFFFFu, v, off);
        if (lane == 0) out[0] = (float)(v / (double)B);
    }
}

extern "C" void kernel_launch(void* const* d_in, const int* in_sizes, int n_in,
                              void* d_out, int out_size) {
    const float* logits = (const float*)d_in[0];
    const int*   y      = (const int*)d_in[1];
    float* out = (float*)d_out;
    int B = in_sizes[1];           // label count = number of rows

    opcel_pass1<<<NBLOCKS, NTHREADS>>>(logits, y, B);
    opcel_pass2<<<1, NTHREADS>>>(out, B);
}

// round 5
// speedup vs baseline: 1.0094x; 1.0094x over previous
#include <cuda_runtime.h>
#include <cuda_bf16.h>

// ---------------------------------------------------------------------------
// OrdinalPeakedCELoss fused single-kernel version.
//  - Block tile = 1024 rows (256 thr x 4 rows). Logits staged to smem via
//    fully-coalesced float4 loads (1 L1 wavefront / 128B line vs 9x before).
//  - Row compute reads smem at stride 9 words (conflict-free).
//  - Per-block partial -> g_partials; last arriving block (atomic counter)
//    sums all partials in double in a fixed order -> deterministic.
//  - Counter self-resets so the kernel is graph-replay safe.
// ---------------------------------------------------------------------------

#define KCLS 9
#define NTHREADS 256
#define ROWS_PER_THREAD 4
#define TILE_ROWS (NTHREADS * ROWS_PER_THREAD)      /* 1024 */
#define TILE_F4   (TILE_ROWS * KCLS / 4)            /* 2304 */
#define F4_PER_THREAD (TILE_F4 / NTHREADS)          /* 9 */
#define MAX_BLOCKS 8192

static __constant__ float c_cw[KCLS] = {
    3.0f/95.0f, 7.0f/95.0f, 10.0f/95.0f, 10.0f/95.0f, 10.0f/95.0f,
    10.0f/95.0f, 10.0f/95.0f, 10.0f/95.0f, 25.0f/95.0f
};

#define ALPHA_C       0.4f
#define W_FAR_C       7.0f
#define DELTA_FAR_C   0.15f
#define W_TAIL_C      9.0f
#define W_LPEAK_C     12.0f
#define PROB_MARGIN_C 0.35f
#define W_EMD_C       1.2f
#define EPS_C         1e-8f
#define INV_LOGK_C    0.45511961331341866f   /* 1/ln(9) */

__device__ float        g_partials[MAX_BLOCKS];
__device__ unsigned int g_count = 0;

__device__ __forceinline__ float row_loss(const float* __restrict__ lp, int y) {
    float l[KCLS];
#pragma unroll
    for (int k = 0; k < KCLS; ++k) l[k] = lp[k];

    float m = l[0];
#pragma unroll
    for (int k = 1; k < KCLS; ++k) m = fmaxf(m, l[k]);

    float e[KCLS];
    float S = 0.0f, ly = 0.0f;
#pragma unroll
    for (int k = 0; k < KCLS; ++k) {
        float ek = __expf(l[k] - m);
        e[k] = ek;
        S += ek;
        if (k == y) ly = l[k];
    }
    float nll  = __logf(S) - (ly - m);
    float invS = __frcp_rn(S);

    float S2 = 0.0f;
#pragma unroll
    for (int k = 0; k < KCLS; ++k) {
        float p = fmaxf(e[k] * invS, EPS_C);
        e[k] = p;
        S2 += p;
    }
    float inv2 = __frcp_rn(S2);

    float py = 0.0f, pl = 0.0f, pr = 0.0f;
    float farmax = 0.0f, tail = 0.0f, emd = 0.0f, csum = 0.0f;
#pragma unroll
    for (int k = 0; k < KCLS; ++k) {
        float p = e[k] * inv2;
        int d  = k - y;
        int ad = (d < 0) ? -d : d;
        if (ad == 0)      py = p;
        else if (d == -1) pl = p;
        else if (d == 1)  pr = p;
        else {
            farmax = fmaxf(farmax, p);
            float w = (float)(ad - 1);
            tail += p * (w * w * w);
        }
        csum += p;
        float t = (k <= y) ? 1.0f : 0.0f;
        float diff = csum - t;
        emd += diff * diff * c_cw[k];
    }

    float farm  = fmaxf(farmax - py + DELTA_FAR_C, 0.0f);
    float nmax  = fmaxf(pl, pr);
    float lpeak = fmaxf(nmax - py + PROB_MARGIN_C, 0.0f);

    return nll * INV_LOGK_C
         + ALPHA_C * (W_FAR_C * farm + W_TAIL_C * tail
                      + W_LPEAK_C * lpeak + W_EMD_C * emd);
}

__global__ __launch_bounds__(NTHREADS)
void opcel_fused(const float4* __restrict__ logits4,
                 const int*    __restrict__ y,
                 float*        __restrict__ out,
                 int B, int nblocks) {
    __shared__ float s_log[TILE_ROWS * KCLS];    /* 36 KB */
    __shared__ float s_red[NTHREADS / 32];
    __shared__ int   s_last;

    const int tid = threadIdx.x;
    const long long total_f4 = ((long long)B * KCLS) >> 2;
    const long long base_f4  = (long long)blockIdx.x * TILE_F4;
    const int row_base = blockIdx.x * TILE_ROWS;

    // Prefetch labels (coalesced) to overlap with the staging loads.
    int yy[ROWS_PER_THREAD];
#pragma unroll
    for (int j = 0; j < ROWS_PER_THREAD; ++j) {
        int r = row_base + tid + j * NTHREADS;
        yy[j] = (r < B) ? __ldg(&y[r]) : 0;
    }

    // Stage the tile: 9 float4 per thread, perfectly coalesced.
#pragma unroll
    for (int i = 0; i < F4_PER_THREAD; ++i) {
        long long g = base_f4 + tid + i * NTHREADS;
        float4 v = make_float4(0.f, 0.f, 0.f, 0.f);
        if (g < total_f4) v = __ldg(&logits4[g]);
        *(float4*)&s_log[(tid + i * NTHREADS) * 4] = v;
    }
    __syncthreads();

    // Compute 4 rows per thread; smem row base stride = 9 words -> no conflicts.
    float acc = 0.0f;
#pragma unroll
    for (int j = 0; j < ROWS_PER_THREAD; ++j) {
        int lr = tid + j * NTHREADS;
        int r  = row_base + lr;
        if (r < B) acc += row_loss(&s_log[lr * KCLS], yy[j]);
    }

    // Block reduction
#pragma unroll
    for (int off = 16; off > 0; off >>= 1)
        acc += __shfl_down_sync(0xFFFFFFFFu, acc, off);
    int lane = tid & 31, wid = tid >> 5;
    if (lane == 0) s_red[wid] = acc;
    __syncthreads();
    if (tid == 0) {
        float v = 0.0f;
#pragma unroll
        for (int w = 0; w < NTHREADS / 32; ++w) v += s_red[w];
        g_partials[blockIdx.x] = v;
        __threadfence();
        unsigned int t = atomicAdd(&g_count, 1u);
        s_last = (t == (unsigned int)(nblocks - 1));
    }
    __syncthreads();

    // Last block performs the final deterministic reduction in double.
    if (s_last) {
        double d = 0.0;
        for (int i = tid; i < nblocks; i += NTHREADS)
            d += (double)g_partials[i];
#pragma unroll
        for (int off = 16; off > 0; off >>= 1)
            d += __shfl_down_sync(0xFFFFFFFFu, d, off);

        __shared__ double s_d[NTHREADS / 32];
        if (lane == 0) s_d[wid] = d;
        __syncthreads();
        if (tid == 0) {
            double tot = 0.0;
#pragma unroll
            for (int w = 0; w < NTHREADS / 32; ++w) tot += s_d[w];
            out[0] = (float)(tot / (double)B);
            g_count = 0;   /* self-reset for next graph replay */
        }
    }
}

extern "C" void kernel_launch(void* const* d_in, const int* in_sizes, int n_in,
                              void* d_out, int out_size) {
    const float4* logits4 = (const float4*)d_in[0];
    const int*    y       = (const int*)d_in[1];
    float* out = (float*)d_out;
    int B = in_sizes[1];                         /* rows */

    int nblocks = (B + TILE_ROWS - 1) / TILE_ROWS;   /* 4096 for B=4M */
    if (nblocks > MAX_BLOCKS) nblocks = MAX_BLOCKS;  /* safety; B=4M fits */

    opcel_fused<<<nblocks, NTHREADS>>>(logits4, y, out, B, nblocks);
}